// round 17
// baseline (speedup 1.0000x reference)
#include <cuda_runtime.h>

#define NUM_CLS 32000
#define BATCH   4096
#define C4      (NUM_CLS / 4)   // 8000 float4 per row
#define THREADS 512
#define NWARP   (THREADS / 32)  // 16
#define NBLOCKS 592             // 148 SMs x 4 resident CTAs — persistent grid
#define MAXROWS 7               // ceil(4096/592)
#define FXSCALE 1048576.0f      // 2^20 fixed-point scale for the row results

// Deterministic fixed-point accumulator: integer atomicAdd is associative
// and commutative -> bit-identical result regardless of completion order.
// Last block resets both for graph replays.
__device__ unsigned long long g_sum;
__device__ unsigned int       g_done;

__global__ __launch_bounds__(THREADS, 4)
void rce_fused_kernel(const float* __restrict__ inp,
                      const float* __restrict__ tgt,
                      float* __restrict__ out)
{
    const int wid = threadIdx.x >> 5;
    const int lid = threadIdx.x & 31;

    // Per-row per-warp partials for ALL of this block's rows. No barrier in
    // the row loop: each warp writes only its own slot; all cross-warp
    // combining is deferred to a single sync at the end.
    __shared__ float     sh_s[MAXROWS][NWARP];
    __shared__ float     sh_e[MAXROWS][NWARP];
    __shared__ unsigned  sh_b[MAXROWS][NWARP];
    __shared__ unsigned  sh_i[MAXROWS][NWARP];
    __shared__ bool      sh_last;

    int k = 0;
    for (int row = blockIdx.x; row < BATCH; row += NBLOCKS, ++k) {
        const float4* ip = reinterpret_cast<const float4*>(inp + (size_t)row * NUM_CLS);
        const float4* tp = reinterpret_cast<const float4*>(tgt + (size_t)row * NUM_CLS);

        float s_sum = 0.f;                 // sum of x
        float e_sum = 0.f;                 // sum of exp(-x)
        unsigned cur_bits = 0xffffffffu;   // running min of target bits (t >= 0
        unsigned cur_idx  = 0u;            //  -> float bits order-preserving)

        #pragma unroll 4
        for (int i = threadIdx.x; i < C4; i += THREADS) {
            const float4 x = ip[i];
            const float4 t = tp[i];

            s_sum += (x.x + x.y) + (x.z + x.w);
            e_sum += (__expf(-x.x) + __expf(-x.y)) + (__expf(-x.z) + __expf(-x.w));

            const unsigned b0 = __float_as_uint(t.x);
            const unsigned b1 = __float_as_uint(t.y);
            const unsigned b2 = __float_as_uint(t.z);
            const unsigned b3 = __float_as_uint(t.w);
            // Quad-local argmin, first index wins ties.
            const unsigned m01 = min(b0, b1);
            const unsigned i01 = (b1 < b0) ? 1u : 0u;
            const unsigned m23 = min(b2, b3);
            const unsigned i23 = (b3 < b2) ? 3u : 2u;
            const unsigned m   = min(m01, m23);
            const unsigned iq  = (m23 < m01) ? i23 : i01;
            // Iterations ascend per thread -> strict < keeps earlier index.
            if (m < cur_bits) { cur_bits = m; cur_idx = (unsigned)i * 4u + iq; }
        }

        // Warp reduce. Value tie -> smaller index (global first occurrence).
        #pragma unroll
        for (int o = 16; o > 0; o >>= 1) {
            s_sum += __shfl_xor_sync(0xffffffffu, s_sum, o);
            e_sum += __shfl_xor_sync(0xffffffffu, e_sum, o);
            const unsigned ob = __shfl_xor_sync(0xffffffffu, cur_bits, o);
            const unsigned oi = __shfl_xor_sync(0xffffffffu, cur_idx,  o);
            if (ob < cur_bits || (ob == cur_bits && oi < cur_idx)) {
                cur_bits = ob; cur_idx = oi;
            }
        }

        // Deposit this warp's partial for row k. No barrier — next row
        // starts immediately; warps drift freely.
        if (lid == 0) { sh_s[k][wid] = s_sum; sh_e[k][wid] = e_sum;
                        sh_b[k][wid] = cur_bits; sh_i[k][wid] = cur_idx; }
    }
    const int nrows = k;   // 6 or 7

    __syncthreads();   // single barrier: all partials deposited

    // Combine phase: warp w retires row w (parallel combines + xi loads),
    // publishing its row directly with one integer atomic.
    if (wid < nrows) {
        const int row = blockIdx.x + wid * NBLOCKS;
        const bool live = (lid < NWARP);
        float S = live ? sh_s[wid][lid] : 0.f;
        float E = live ? sh_e[wid][lid] : 0.f;
        unsigned B = live ? sh_b[wid][lid] : 0xffffffffu;
        unsigned I = live ? sh_i[wid][lid] : 0xffffffffu;
        #pragma unroll
        for (int o = 8; o > 0; o >>= 1) {
            S += __shfl_xor_sync(0xffffffffu, S, o);
            E += __shfl_xor_sync(0xffffffffu, E, o);
            const unsigned ob = __shfl_xor_sync(0xffffffffu, B, o);
            const unsigned oi = __shfl_xor_sync(0xffffffffu, I, o);
            if (ob < B || (ob == B && oi < I)) { B = ob; I = oi; }
        }
        if (lid == 0) {
            const float xi = inp[(size_t)row * NUM_CLS + I];
            // r_b = S_b + (C-1)*log(E_b) - x[b, idx]
            const float r = S + (float)(NUM_CLS - 1) * logf(E) - xi;
            atomicAdd(&g_sum, (unsigned long long)(long long)__float2ll_rn(r * FXSCALE));
            // Fence in the PUBLISHING thread: orders this thread's g_sum
            // atomic before anything that follows the barrier below
            // (thread 0's g_done increment). A fence by thread 0 alone
            // would not order other threads' atomics.
            __threadfence();
        }
    }
    __syncthreads();

    // Count this block done; last block converts and writes the output.
    if (threadIdx.x == 0) {
        const unsigned prev = atomicAdd(&g_done, 1u);
        sh_last = (prev == (unsigned)(NBLOCKS - 1));
    }
    __syncthreads();

    if (sh_last && threadIdx.x == 0) {
        const long long total = (long long)g_sum;
        // loss = (RATIO / (B*(C-1))) * sum_b r_b ; RATIO = 1.0
        out[0] = (float)((double)total / (double)FXSCALE
                         / ((double)BATCH * (double)(NUM_CLS - 1)));
        g_sum  = 0ull;   // reset for next graph replay
        g_done = 0u;
    }
}

extern "C" void kernel_launch(void* const* d_in, const int* in_sizes, int n_in,
                              void* d_out, int out_size)
{
    const float* inp = (const float*)d_in[0];   // input  [B, C] f32
    const float* tgt = (const float*)d_in[1];   // target [B, C] f32
    float* out = (float*)d_out;                 // scalar f32

    rce_fused_kernel<<<NBLOCKS, THREADS>>>(inp, tgt, out);
}